// round 6
// baseline (speedup 1.0000x reference)
#include <cuda_runtime.h>

#define NB    100   // neighbors
#define NF    13    // features
#define WPB   4     // warps per block
#define TPB   (WPB * 32)
#define GB    16    // batches per block (4 rounds x 4 warps)

// Branch-free Jacobi rotation on symmetric M, accumulating V.
__device__ __forceinline__ void jrot(float M[3][3], float V[3][3], int p, int q) {
    float apq = M[p][q];
    float D   = 0.5f * (M[q][q] - M[p][p]);
    float hyp = sqrtf(fmaf(D, D, fmaf(apq, apq, 1e-38f)));
    float t   = __fdividef(apq, copysignf(fabsf(D) + hyp, D));
    float c   = rsqrtf(fmaf(t, t, 1.0f));
    float s   = t * c;
    float tapq = t * apq;
    M[p][p] -= tapq;
    M[q][q] += tapq;
    M[p][q] = 0.0f; M[q][p] = 0.0f;
    const int r = 3 - p - q;
    float mrp = M[r][p], mrq = M[r][q];
    M[r][p] = fmaf(c, mrp, -s * mrq); M[p][r] = M[r][p];
    M[r][q] = fmaf(s, mrp,  c * mrq); M[q][r] = M[r][q];
#pragma unroll
    for (int i = 0; i < 3; i++) {
        float vip = V[i][p], viq = V[i][q];
        V[i][p] = fmaf(c, vip, -s * viq);
        V[i][q] = fmaf(s, vip,  c * viq);
    }
}

__global__ void __launch_bounds__(TPB) svd_align_kernel(
    const float* __restrict__ in,
    const float* __restrict__ pa,
    const float* __restrict__ pb,
    const float* __restrict__ pshift,
    float* __restrict__ out,
    int B)
{
    __shared__ float buf[WPB][NB * NF];   // per-warp staging, reused each round
    __shared__ float sums[GB][17];        // 16 reduced values per batch (padded)
    __shared__ float rt[GB][13];          // R(9)+t(3) per batch (padded)

    const int tid  = threadIdx.x;
    const int wid  = tid >> 5;
    const int lane = tid & 31;
    const int base = blockIdx.x * GB;

    const float a     = pa[0];
    const float bbias = pb[0];
    const float shift = pshift[0];

    // ================= Phase 1: stage + reduce, 4 rounds =================
#pragma unroll
    for (int j = 0; j < 4; j++) {
        const int bl    = j * WPB + wid;
        const int batch = base + bl;
        if (batch < B) {
            const float4* src = (const float4*)(in + (size_t)batch * (NB * NF));
            float4* dst = (float4*)buf[wid];
#pragma unroll
            for (int i = 0; i < 11; i++) {
                int q = i * 32 + lane;
                if (q < 325) dst[q] = src[q];
            }
        }
        __syncwarp();

        float acc[16];
#pragma unroll
        for (int k = 0; k < 16; k++) acc[k] = 0.0f;

        if (batch < B) {
            const float* sm = buf[wid];
#pragma unroll
            for (int c = 0; c < 4; c++) {
                int n = c * 32 + lane;
                if (c < 3 || lane < NB - 96) {
                    const float* r = &sm[n * NF];
                    float w = fmaf(a, r[0], bbias);
                    w = fmaxf(w, 0.0f) + 1e-8f;
                    float v1[3], v2[3], wv2[3];
#pragma unroll
                    for (int k = 0; k < 3; k++) {
                        v1[k] = fmaf(shift, r[7 + k],  r[1 + k]);
                        v2[k] = fmaf(shift, r[10 + k], r[4 + k]);
                    }
                    acc[0] += w;
#pragma unroll
                    for (int k = 0; k < 3; k++) {
                        acc[1 + k] = fmaf(w, v1[k], acc[1 + k]);
                        wv2[k]     = w * v2[k];
                        acc[4 + k] += wv2[k];
                    }
#pragma unroll
                    for (int k = 0; k < 3; k++)
#pragma unroll
                        for (int m = 0; m < 3; m++)
                            acc[7 + k * 3 + m] = fmaf(wv2[k], v1[m], acc[7 + k * 3 + m]);
                }
            }
        }

        // butterfly reduce: 16 values over 32 lanes (5 steps); all lanes converged
        float r8[8];
#pragma unroll
        for (int k = 0; k < 8; k++) {
            float snd = (lane & 1) ? acc[k] : acc[k + 8];
            float rcv = __shfl_xor_sync(0xffffffffu, snd, 1);
            float kep = (lane & 1) ? acc[k + 8] : acc[k];
            r8[k] = kep + rcv;
        }
        float r4[4];
#pragma unroll
        for (int k = 0; k < 4; k++) {
            float snd = (lane & 2) ? r8[k] : r8[k + 4];
            float rcv = __shfl_xor_sync(0xffffffffu, snd, 2);
            float kep = (lane & 2) ? r8[k + 4] : r8[k];
            r4[k] = kep + rcv;
        }
        float r2[2];
#pragma unroll
        for (int k = 0; k < 2; k++) {
            float snd = (lane & 4) ? r4[k] : r4[k + 2];
            float rcv = __shfl_xor_sync(0xffffffffu, snd, 4);
            float kep = (lane & 4) ? r4[k + 2] : r4[k];
            r2[k] = kep + rcv;
        }
        float snd1 = (lane & 8) ? r2[0] : r2[1];
        float rcv1 = __shfl_xor_sync(0xffffffffu, snd1, 8);
        float kep1 = (lane & 8) ? r2[1] : r2[0];
        float red  = kep1 + rcv1;
        red += __shfl_xor_sync(0xffffffffu, red, 16);
        // lane l (0..15) now holds sum index rev4(l) for this batch

        if (lane < 16 && batch < B) sums[bl][lane] = red;
        __syncwarp();
    }
    __syncthreads();

    // ================= Phase 2: SVD, one batch per thread =================
    if (tid < GB && base + tid < B) {
        // f[k] lives at sums[tid][rev4(k)]
        const int rev[16] = {0,8,4,12,2,10,6,14,1,9,5,13,3,11,7,15};
        float f[16];
#pragma unroll
        for (int k = 0; k < 16; k++) f[k] = sums[tid][rev[k]];

        const float inv_w = __fdividef(1.0f, f[0]);
        float v1c[3], v2c[3];
#pragma unroll
        for (int k = 0; k < 3; k++) { v1c[k] = f[1 + k] * inv_w; v2c[k] = f[4 + k] * inv_w; }

        float A[3][3];
#pragma unroll
        for (int k = 0; k < 3; k++)
#pragma unroll
            for (int m = 0; m < 3; m++)
                A[k][m] = fmaf(-f[4 + k] * inv_w, f[1 + m], f[7 + k * 3 + m]);

        float M[3][3];
#pragma unroll
        for (int i = 0; i < 3; i++)
#pragma unroll
            for (int m = 0; m < 3; m++) {
                float s = A[0][i] * A[0][m];
                s = fmaf(A[1][i], A[1][m], s);
                s = fmaf(A[2][i], A[2][m], s);
                M[i][m] = s;
            }

        float V[3][3] = {{1,0,0},{0,1,0},{0,0,1}};
#pragma unroll
        for (int sweep = 0; sweep < 4; sweep++) {
            jrot(M, V, 0, 1);
            jrot(M, V, 0, 2);
            jrot(M, V, 1, 2);
        }

        // branch-free descending eigen-sort
        float e0 = M[0][0], e1 = M[1][1], e2 = M[2][2];
        float c0[3] = { V[0][0], V[1][0], V[2][0] };
        float c1[3] = { V[0][1], V[1][1], V[2][1] };
        float c2[3] = { V[0][2], V[1][2], V[2][2] };
        {
            bool sw = e0 < e1;
            float te = sw ? e1 : e0; e1 = sw ? e0 : e1; e0 = te;
#pragma unroll
            for (int i = 0; i < 3; i++) { float tv = sw ? c1[i] : c0[i]; c1[i] = sw ? c0[i] : c1[i]; c0[i] = tv; }
        }
        {
            bool sw = e1 < e2;
            float te = sw ? e2 : e1; e2 = sw ? e1 : e2; e1 = te;
#pragma unroll
            for (int i = 0; i < 3; i++) { float tv = sw ? c2[i] : c1[i]; c2[i] = sw ? c1[i] : c2[i]; c1[i] = tv; }
        }
        {
            bool sw = e0 < e1;
            float te = sw ? e1 : e0; e1 = sw ? e0 : e1; e0 = te;
#pragma unroll
            for (int i = 0; i < 3; i++) { float tv = sw ? c1[i] : c0[i]; c1[i] = sw ? c0[i] : c1[i]; c0[i] = tv; }
        }

        // U: u0 = norm(A c0); u1 = orth-norm(A c1); u2 = u0 x u1
        float u0[3], u1[3], u2[3];
#pragma unroll
        for (int i = 0; i < 3; i++) {
            u0[i] = A[i][0] * c0[0] + A[i][1] * c0[1] + A[i][2] * c0[2];
            u1[i] = A[i][0] * c1[0] + A[i][1] * c1[1] + A[i][2] * c1[2];
        }
        float n0 = rsqrtf(fmaf(u0[0], u0[0], fmaf(u0[1], u0[1], fmaf(u0[2], u0[2], 1e-30f))));
#pragma unroll
        for (int i = 0; i < 3; i++) u0[i] *= n0;
        float d01 = u0[0]*u1[0] + u0[1]*u1[1] + u0[2]*u1[2];
#pragma unroll
        for (int i = 0; i < 3; i++) u1[i] = fmaf(-d01, u0[i], u1[i]);
        float n1 = rsqrtf(fmaf(u1[0], u1[0], fmaf(u1[1], u1[1], fmaf(u1[2], u1[2], 1e-30f))));
#pragma unroll
        for (int i = 0; i < 3; i++) u1[i] *= n1;
        u2[0] = u0[1]*u1[2] - u0[2]*u1[1];
        u2[1] = u0[2]*u1[0] - u0[0]*u1[2];
        u2[2] = u0[0]*u1[1] - u0[1]*u1[0];

        float detV =
            c0[0] * (c1[1]*c2[2] - c1[2]*c2[1]) -
            c1[0] * (c0[1]*c2[2] - c0[2]*c2[1]) +
            c2[0] * (c0[1]*c1[2] - c0[2]*c1[1]);
        float d3 = (detV > 0.0f) ? 1.0f : -1.0f;

        float c2d[3] = { d3 * c2[0], d3 * c2[1], d3 * c2[2] };
        float R[3][3];
#pragma unroll
        for (int i = 0; i < 3; i++) {
            R[i][0] = c0[i]*u0[0] + c1[i]*u1[0] + c2d[i]*u2[0];
            R[i][1] = c0[i]*u0[1] + c1[i]*u1[1] + c2d[i]*u2[1];
            R[i][2] = c0[i]*u0[2] + c1[i]*u1[2] + c2d[i]*u2[2];
        }
#pragma unroll
        for (int i = 0; i < 3; i++) {
#pragma unroll
            for (int m = 0; m < 3; m++) rt[tid][i * 3 + m] = R[i][m];
            rt[tid][9 + i] = v1c[i] - (R[i][0]*v2c[0] + R[i][1]*v2c[1] + R[i][2]*v2c[2]);
        }
    }
    __syncthreads();

    // ================= Phase 3: re-stage (L2-hot) + apply, 4 rounds =================
#pragma unroll
    for (int j = 0; j < 4; j++) {
        const int bl    = j * WPB + wid;
        const int batch = base + bl;
        if (batch < B) {
            const float4* src = (const float4*)(in + (size_t)batch * (NB * NF));
            float4* dst = (float4*)buf[wid];
#pragma unroll
            for (int i = 0; i < 11; i++) {
                int q = i * 32 + lane;
                if (q < 325) dst[q] = src[q];
            }
        }
        __syncwarp();

        if (batch < B) {
            float Rt[12];
#pragma unroll
            for (int k = 0; k < 12; k++) Rt[k] = rt[bl][k];   // broadcast LDS

            const float* sm = buf[wid];
            float* ob = out + (size_t)batch * (NB * 6);
#pragma unroll
            for (int c = 0; c < 4; c++) {
                int n = c * 32 + lane;
                if (c < 3 || lane < NB - 96) {
                    const float* row = &sm[n * NF];
                    float x0 = row[4],  x1 = row[5],  x2 = row[6];
                    float m0 = row[10], m1 = row[11], m2 = row[12];
                    float2 o0, o1, o2;
                    o0.x = fmaf(Rt[0], x0, fmaf(Rt[1], x1, fmaf(Rt[2], x2, Rt[9])));
                    o0.y = fmaf(Rt[3], x0, fmaf(Rt[4], x1, fmaf(Rt[5], x2, Rt[10])));
                    o1.x = fmaf(Rt[6], x0, fmaf(Rt[7], x1, fmaf(Rt[8], x2, Rt[11])));
                    o1.y = fmaf(Rt[0], m0, fmaf(Rt[1], m1, Rt[2] * m2));
                    o2.x = fmaf(Rt[3], m0, fmaf(Rt[4], m1, Rt[5] * m2));
                    o2.y = fmaf(Rt[6], m0, fmaf(Rt[7], m1, Rt[8] * m2));
                    float2* op = (float2*)(ob + n * 6);
                    op[0] = o0; op[1] = o1; op[2] = o2;
                }
            }
        }
        __syncwarp();
    }
}

extern "C" void kernel_launch(void* const* d_in, const int* in_sizes, int n_in,
                              void* d_out, int out_size) {
    const float* net   = (const float*)d_in[0];
    const float* a     = (const float*)d_in[1];
    const float* b     = (const float*)d_in[2];
    const float* shift = (const float*)d_in[3];
    float* out = (float*)d_out;

    int B = in_sizes[0] / (NB * NF);   // 100000
    int grid = (B + GB - 1) / GB;
    svd_align_kernel<<<grid, TPB>>>(net, a, b, shift, out, B);
}

// round 7
// speedup vs baseline: 1.6890x; 1.6890x over previous
#include <cuda_runtime.h>

#define NB    100   // neighbors
#define NF    13    // features
#define WPB   4     // warps per block
#define TPB   (WPB * 32)
// each warp processes 2 consecutive batches through ONE 5.2KB staging buffer

// Branch-free Jacobi rotation on symmetric M, accumulating V.
__device__ __forceinline__ void jrot(float M[3][3], float V[3][3], int p, int q) {
    float apq = M[p][q];
    float D   = 0.5f * (M[q][q] - M[p][p]);
    float hyp = sqrtf(fmaf(D, D, fmaf(apq, apq, 1e-38f)));
    float t   = __fdividef(apq, copysignf(fabsf(D) + hyp, D));
    float c   = rsqrtf(fmaf(t, t, 1.0f));
    float s   = t * c;
    float tapq = t * apq;
    M[p][p] -= tapq;
    M[q][q] += tapq;
    M[p][q] = 0.0f; M[q][p] = 0.0f;
    const int r = 3 - p - q;
    float mrp = M[r][p], mrq = M[r][q];
    M[r][p] = fmaf(c, mrp, -s * mrq); M[p][r] = M[r][p];
    M[r][q] = fmaf(s, mrp,  c * mrq); M[q][r] = M[r][q];
#pragma unroll
    for (int i = 0; i < 3; i++) {
        float vip = V[i][p], viq = V[i][q];
        V[i][p] = fmaf(c, vip, -s * viq);
        V[i][q] = fmaf(s, vip,  c * viq);
    }
}

// stage one batch row (1300 floats) into the warp's SMEM buffer
__device__ __forceinline__ void stage(const float* __restrict__ in, int batch,
                                      float* __restrict__ sm, int lane) {
    const float4* src = (const float4*)(in + (size_t)batch * (NB * NF));
    float4* dst = (float4*)sm;
#pragma unroll
    for (int i = 0; i < 11; i++) {
        int q = i * 32 + lane;
        if (q < 325) dst[q] = src[q];
    }
}

// reduce 16 weighted sums over 100 neighbors from SMEM; returns per-lane
// butterfly result: lane l holds sum index rev4(l&15) (halves identical)
__device__ __forceinline__ float reduce_batch(const float* __restrict__ sm, int lane,
                                              float a, float bbias, float shift) {
    float acc[16];
#pragma unroll
    for (int k = 0; k < 16; k++) acc[k] = 0.0f;

#pragma unroll
    for (int c = 0; c < 4; c++) {
        int n = c * 32 + lane;
        if (c < 3 || lane < NB - 96) {
            const float* r = &sm[n * NF];
            float w = fmaf(a, r[0], bbias);
            w = fmaxf(w, 0.0f) + 1e-8f;
            float v1[3], v2[3], wv2[3];
#pragma unroll
            for (int k = 0; k < 3; k++) {
                v1[k] = fmaf(shift, r[7 + k],  r[1 + k]);
                v2[k] = fmaf(shift, r[10 + k], r[4 + k]);
            }
            acc[0] += w;
#pragma unroll
            for (int k = 0; k < 3; k++) {
                acc[1 + k] = fmaf(w, v1[k], acc[1 + k]);
                wv2[k]     = w * v2[k];
                acc[4 + k] += wv2[k];
            }
#pragma unroll
            for (int k = 0; k < 3; k++)
#pragma unroll
                for (int m = 0; m < 3; m++)
                    acc[7 + k * 3 + m] = fmaf(wv2[k], v1[m], acc[7 + k * 3 + m]);
        }
    }

    float r8[8];
#pragma unroll
    for (int k = 0; k < 8; k++) {
        float snd = (lane & 1) ? acc[k] : acc[k + 8];
        float rcv = __shfl_xor_sync(0xffffffffu, snd, 1);
        float kep = (lane & 1) ? acc[k + 8] : acc[k];
        r8[k] = kep + rcv;
    }
    float r4[4];
#pragma unroll
    for (int k = 0; k < 4; k++) {
        float snd = (lane & 2) ? r8[k] : r8[k + 4];
        float rcv = __shfl_xor_sync(0xffffffffu, snd, 2);
        float kep = (lane & 2) ? r8[k + 4] : r8[k];
        r4[k] = kep + rcv;
    }
    float r2[2];
#pragma unroll
    for (int k = 0; k < 2; k++) {
        float snd = (lane & 4) ? r4[k] : r4[k + 2];
        float rcv = __shfl_xor_sync(0xffffffffu, snd, 4);
        float kep = (lane & 4) ? r4[k + 2] : r4[k];
        r2[k] = kep + rcv;
    }
    float snd1 = (lane & 8) ? r2[0] : r2[1];
    float rcv1 = __shfl_xor_sync(0xffffffffu, snd1, 8);
    float kep1 = (lane & 8) ? r2[1] : r2[0];
    float red  = kep1 + rcv1;
    red += __shfl_xor_sync(0xffffffffu, red, 16);
    return red;
}

// apply R,t (in rt[12]) to batch data in sm, write to out
__device__ __forceinline__ void apply_batch(const float* __restrict__ sm,
                                            const float* __restrict__ rt,
                                            float* __restrict__ out, int batch, int lane) {
    float Rt[12];
#pragma unroll
    for (int k = 0; k < 12; k++) Rt[k] = rt[k];    // LDS broadcast
    float* ob = out + (size_t)batch * (NB * 6);
#pragma unroll
    for (int c = 0; c < 4; c++) {
        int n = c * 32 + lane;
        if (c < 3 || lane < NB - 96) {
            const float* row = &sm[n * NF];
            float x0 = row[4],  x1 = row[5],  x2 = row[6];
            float m0 = row[10], m1 = row[11], m2 = row[12];
            float2 o0, o1, o2;
            o0.x = fmaf(Rt[0], x0, fmaf(Rt[1], x1, fmaf(Rt[2], x2, Rt[9])));
            o0.y = fmaf(Rt[3], x0, fmaf(Rt[4], x1, fmaf(Rt[5], x2, Rt[10])));
            o1.x = fmaf(Rt[6], x0, fmaf(Rt[7], x1, fmaf(Rt[8], x2, Rt[11])));
            o1.y = fmaf(Rt[0], m0, fmaf(Rt[1], m1, Rt[2] * m2));
            o2.x = fmaf(Rt[3], m0, fmaf(Rt[4], m1, Rt[5] * m2));
            o2.y = fmaf(Rt[6], m0, fmaf(Rt[7], m1, Rt[8] * m2));
            float2* op = (float2*)(ob + n * 6);
            op[0] = o0; op[1] = o1; op[2] = o2;
        }
    }
}

__global__ void __launch_bounds__(TPB) svd_align_kernel(
    const float* __restrict__ in,
    const float* __restrict__ pa,
    const float* __restrict__ pb,
    const float* __restrict__ pshift,
    float* __restrict__ out,
    int B)
{
    __shared__ float buf[WPB][NB * NF];   // 5.2KB per warp, reused for both batches
    __shared__ float rtbuf[WPB][2][13];   // R(9)+t(3) per (warp, sub-batch)

    const int wid  = threadIdx.x >> 5;
    const int lane = threadIdx.x & 31;
    const int l15  = lane & 15;
    const int sub  = lane >> 4;
    const int b0   = (blockIdx.x * WPB + wid) * 2;   // this warp's first batch
    if (b0 >= B) return;
    const int b1   = b0 + 1;
    const bool b1ok = b1 < B;

    const float a     = pa[0];
    const float bbias = pb[0];
    const float shift = pshift[0];

    float* sm = buf[wid];

    // ---- batch0: stage + reduce ----
    stage(in, b0, sm, lane);
    __syncwarp();
    float red0 = reduce_batch(sm, lane, a, bbias, shift);
    __syncwarp();

    // ---- batch1: stage + reduce (overwrites buffer) ----
    if (b1ok) stage(in, b1, sm, lane);
    __syncwarp();
    float red1 = b1ok ? reduce_batch(sm, lane, a, bbias, shift) : 0.0f;

    // ---- gather 16 sums for this lane's sub-batch ----
    const int hbase = lane & 16;
    float redsel = sub ? red1 : red0;
    float f[16];
    f[0]  = __shfl_sync(0xffffffffu, redsel, hbase | 0);
    f[1]  = __shfl_sync(0xffffffffu, redsel, hbase | 8);
    f[2]  = __shfl_sync(0xffffffffu, redsel, hbase | 4);
    f[3]  = __shfl_sync(0xffffffffu, redsel, hbase | 12);
    f[4]  = __shfl_sync(0xffffffffu, redsel, hbase | 2);
    f[5]  = __shfl_sync(0xffffffffu, redsel, hbase | 10);
    f[6]  = __shfl_sync(0xffffffffu, redsel, hbase | 6);
    f[7]  = __shfl_sync(0xffffffffu, redsel, hbase | 14);
    f[8]  = __shfl_sync(0xffffffffu, redsel, hbase | 1);
    f[9]  = __shfl_sync(0xffffffffu, redsel, hbase | 9);
    f[10] = __shfl_sync(0xffffffffu, redsel, hbase | 5);
    f[11] = __shfl_sync(0xffffffffu, redsel, hbase | 13);
    f[12] = __shfl_sync(0xffffffffu, redsel, hbase | 3);
    f[13] = __shfl_sync(0xffffffffu, redsel, hbase | 11);
    f[14] = __shfl_sync(0xffffffffu, redsel, hbase | 7);
    f[15] = __shfl_sync(0xffffffffu, redsel, hbase | 15);

    // ---- convergent SVD: lane 0 -> batch0, lane 16 -> batch1 ----
    if (l15 == 0 && (sub == 0 || b1ok)) {
        const float inv_w = __fdividef(1.0f, f[0]);
        float v1c[3], v2c[3];
#pragma unroll
        for (int k = 0; k < 3; k++) { v1c[k] = f[1 + k] * inv_w; v2c[k] = f[4 + k] * inv_w; }

        float A[3][3];
#pragma unroll
        for (int k = 0; k < 3; k++)
#pragma unroll
            for (int m = 0; m < 3; m++)
                A[k][m] = fmaf(-f[4 + k] * inv_w, f[1 + m], f[7 + k * 3 + m]);

        float M[3][3];
#pragma unroll
        for (int i = 0; i < 3; i++)
#pragma unroll
            for (int m = 0; m < 3; m++) {
                float s = A[0][i] * A[0][m];
                s = fmaf(A[1][i], A[1][m], s);
                s = fmaf(A[2][i], A[2][m], s);
                M[i][m] = s;
            }

        float V[3][3] = {{1,0,0},{0,1,0},{0,0,1}};
#pragma unroll
        for (int sweep = 0; sweep < 4; sweep++) {
            jrot(M, V, 0, 1);
            jrot(M, V, 0, 2);
            jrot(M, V, 1, 2);
        }

        // branch-free descending eigen-sort
        float e0 = M[0][0], e1 = M[1][1], e2 = M[2][2];
        float c0[3] = { V[0][0], V[1][0], V[2][0] };
        float c1[3] = { V[0][1], V[1][1], V[2][1] };
        float c2[3] = { V[0][2], V[1][2], V[2][2] };
        {
            bool sw = e0 < e1;
            float te = sw ? e1 : e0; e1 = sw ? e0 : e1; e0 = te;
#pragma unroll
            for (int i = 0; i < 3; i++) { float tv = sw ? c1[i] : c0[i]; c1[i] = sw ? c0[i] : c1[i]; c0[i] = tv; }
        }
        {
            bool sw = e1 < e2;
            float te = sw ? e2 : e1; e2 = sw ? e1 : e2; e1 = te;
#pragma unroll
            for (int i = 0; i < 3; i++) { float tv = sw ? c2[i] : c1[i]; c2[i] = sw ? c1[i] : c2[i]; c1[i] = tv; }
        }
        {
            bool sw = e0 < e1;
            float te = sw ? e1 : e0; e1 = sw ? e0 : e1; e0 = te;
#pragma unroll
            for (int i = 0; i < 3; i++) { float tv = sw ? c1[i] : c0[i]; c1[i] = sw ? c0[i] : c1[i]; c0[i] = tv; }
        }

        // U: u0 = norm(A c0); u1 = orth-norm(A c1); u2 = u0 x u1
        float u0[3], u1[3], u2[3];
#pragma unroll
        for (int i = 0; i < 3; i++) {
            u0[i] = A[i][0] * c0[0] + A[i][1] * c0[1] + A[i][2] * c0[2];
            u1[i] = A[i][0] * c1[0] + A[i][1] * c1[1] + A[i][2] * c1[2];
        }
        float n0 = rsqrtf(fmaf(u0[0], u0[0], fmaf(u0[1], u0[1], fmaf(u0[2], u0[2], 1e-30f))));
#pragma unroll
        for (int i = 0; i < 3; i++) u0[i] *= n0;
        float d01 = u0[0]*u1[0] + u0[1]*u1[1] + u0[2]*u1[2];
#pragma unroll
        for (int i = 0; i < 3; i++) u1[i] = fmaf(-d01, u0[i], u1[i]);
        float n1 = rsqrtf(fmaf(u1[0], u1[0], fmaf(u1[1], u1[1], fmaf(u1[2], u1[2], 1e-30f))));
#pragma unroll
        for (int i = 0; i < 3; i++) u1[i] *= n1;
        u2[0] = u0[1]*u1[2] - u0[2]*u1[1];
        u2[1] = u0[2]*u1[0] - u0[0]*u1[2];
        u2[2] = u0[0]*u1[1] - u0[1]*u1[0];

        float detV =
            c0[0] * (c1[1]*c2[2] - c1[2]*c2[1]) -
            c1[0] * (c0[1]*c2[2] - c0[2]*c2[1]) +
            c2[0] * (c0[1]*c1[2] - c0[2]*c1[1]);
        float d3 = (detV > 0.0f) ? 1.0f : -1.0f;

        float c2d[3] = { d3 * c2[0], d3 * c2[1], d3 * c2[2] };
        float* rts = rtbuf[wid][sub];
#pragma unroll
        for (int i = 0; i < 3; i++) {
            float Ri0 = c0[i]*u0[0] + c1[i]*u1[0] + c2d[i]*u2[0];
            float Ri1 = c0[i]*u0[1] + c1[i]*u1[1] + c2d[i]*u2[1];
            float Ri2 = c0[i]*u0[2] + c1[i]*u1[2] + c2d[i]*u2[2];
            rts[i * 3 + 0] = Ri0;
            rts[i * 3 + 1] = Ri1;
            rts[i * 3 + 2] = Ri2;
            rts[9 + i] = v1c[i] - (Ri0 * v2c[0] + Ri1 * v2c[1] + Ri2 * v2c[2]);
        }
    }
    __syncwarp();

    // ---- apply batch1 (data still in buffer) ----
    if (b1ok) apply_batch(sm, rtbuf[wid][1], out, b1, lane);

    // ---- re-stage batch0 (warp-local window -> L2 hit) and apply ----
    stage(in, b0, sm, lane);
    __syncwarp();
    apply_batch(sm, rtbuf[wid][0], out, b0, lane);
}

extern "C" void kernel_launch(void* const* d_in, const int* in_sizes, int n_in,
                              void* d_out, int out_size) {
    const float* net   = (const float*)d_in[0];
    const float* a     = (const float*)d_in[1];
    const float* b     = (const float*)d_in[2];
    const float* shift = (const float*)d_in[3];
    float* out = (float*)d_out;

    int B = in_sizes[0] / (NB * NF);   // 100000
    int grid = (B + WPB * 2 - 1) / (WPB * 2);
    svd_align_kernel<<<grid, TPB>>>(net, a, b, shift, out, B);
}